// round 14
// baseline (speedup 1.0000x reference)
#include <cuda_runtime.h>
#include <cuda_bf16.h>
#include <cuda_fp16.h>
#include <cstdint>

// ---------------------------------------------------------------------------
// Problem dims (fixed)
// ---------------------------------------------------------------------------
static constexpr int Mdim = 8192;
static constexpr int Kdim = 2048;
static constexpr int Ndim = 4096;

static constexpr int BM = 128;
static constexpr int BN = 128;            // exactly 1 GroupNorm group
static constexpr int BK = 64;             // fp16 -> 128B rows in smem (SW128)
static constexpr int NSLICE = Kdim / BK;  // 32
static constexpr int NSTAGE = 3;
static constexpr int NTHREADS = 256;      // 8 warps; 2 CTAs/SM -> 4 warps/SMSP

// SW128 swizzle: XOR bits [6:4] with bits [9:7] (conflict-free on 128B rows
// for both cp.async 16B chunks and ldmatrix lane addresses).
__host__ __device__ __forceinline__ uint32_t SWZ(uint32_t o) {
    return o ^ ((o >> 3) & 0x70u);
}

// ---------------------------------------------------------------------------
// Scratch (device globals — no runtime allocation allowed)
// ---------------------------------------------------------------------------
__device__ __align__(1024) __half g_xh[Mdim * Kdim];
__device__ __align__(1024) __half g_wh[Ndim * Kdim];
__device__ unsigned int g_rowmin[Mdim];  // order-preserving uint encoding

// ---------------------------------------------------------------------------
// PTX helpers (sm_80-compatible only: cp.async, ldmatrix, mma.sync)
// ---------------------------------------------------------------------------
__device__ __forceinline__ uint32_t smem_u32(const void* p) {
    uint32_t a;
    asm("{ .reg .u64 t; cvta.to.shared.u64 t, %1; cvt.u32.u64 %0, t; }"
        : "=r"(a) : "l"(p));
    return a;
}
__device__ __forceinline__ void cp_async16(uint32_t s, const void* g) {
    asm volatile("cp.async.cg.shared.global [%0], [%1], 16;" :: "r"(s), "l"(g));
}
__device__ __forceinline__ void cp_commit() {
    asm volatile("cp.async.commit_group;" ::: "memory");
}
template <int N>
__device__ __forceinline__ void cp_wait() {
    asm volatile("cp.async.wait_group %0;" :: "n"(N) : "memory");
}
__device__ __forceinline__ void ldsm_x4(uint32_t (&r)[4], uint32_t addr) {
    asm volatile("ldmatrix.sync.aligned.m8n8.x4.shared.b16 {%0,%1,%2,%3}, [%4];"
                 : "=r"(r[0]), "=r"(r[1]), "=r"(r[2]), "=r"(r[3]) : "r"(addr));
}
__device__ __forceinline__ void mma_f16(float (&c)[4], const uint32_t (&a)[4],
                                        uint32_t b0, uint32_t b1) {
    asm volatile(
        "mma.sync.aligned.m16n8k16.row.col.f32.f16.f16.f32 "
        "{%0,%1,%2,%3}, {%4,%5,%6,%7}, {%8,%9}, {%0,%1,%2,%3};"
        : "+f"(c[0]), "+f"(c[1]), "+f"(c[2]), "+f"(c[3])
        : "r"(a[0]), "r"(a[1]), "r"(a[2]), "r"(a[3]), "r"(b0), "r"(b1));
}

// ---------------------------------------------------------------------------
// Kernel 1: fp32 -> fp16 for x and W; init rowmin
// ---------------------------------------------------------------------------
__global__ void k_convert(const float* __restrict__ x, const float* __restrict__ w) {
    int i = blockIdx.x * blockDim.x + threadIdx.x;
    constexpr int XQ = (Mdim * Kdim) / 4;
    constexpr int WQ = (Ndim * Kdim) / 4;

    if (i < XQ) {
        float4 v = reinterpret_cast<const float4*>(x)[i];
        __half2 h0 = __floats2half2_rn(v.x, v.y);
        __half2 h1 = __floats2half2_rn(v.z, v.w);
        reinterpret_cast<__half2*>(g_xh)[2 * i]     = h0;
        reinterpret_cast<__half2*>(g_xh)[2 * i + 1] = h1;
    }
    if (i < WQ) {
        float4 v = reinterpret_cast<const float4*>(w)[i];
        __half2 h0 = __floats2half2_rn(v.x, v.y);
        __half2 h1 = __floats2half2_rn(v.z, v.w);
        reinterpret_cast<__half2*>(g_wh)[2 * i]     = h0;
        reinterpret_cast<__half2*>(g_wh)[2 * i + 1] = h1;
    }
    if (i < Mdim) g_rowmin[i] = 0xFFFFFFFFu;
}

// ---------------------------------------------------------------------------
// Kernel 2: fp16 mma.sync GEMM + fused bias/GroupNorm/row-min epilogue
// ---------------------------------------------------------------------------
// smem layout (dynamic, 1024-aligned), 100 KB total -> 2 CTAs/SM:
//   [0..511]    bgemm[128] f32
//   [1024..]    gamma[128] f32
//   [2048..]    beta[128]  f32
//   [4096..]    3 stages x 32KB:  A 16K (128 x 128B) | B 16K (128 x 128B)
//   epilogue reuses [4096..] as y[128][132] f32 (67,584 B)
static constexpr int SM_BG    = 0;
static constexpr int SM_GA    = 1024;
static constexpr int SM_BE    = 2048;
static constexpr int SM_STAGE = 4096;
static constexpr int STAGE_BYTES = 32 * 1024;
static constexpr int OFF_A = 0;
static constexpr int OFF_B = 16384;
static constexpr int SMEM_TOTAL = SM_STAGE + NSTAGE * STAGE_BYTES;  // 102400
static constexpr int YSTRIDE = 132;  // floats; odd 16B-quad stride -> low conflicts

__global__ void __launch_bounds__(NTHREADS, 2)
k_gemm_gn(const float* __restrict__ bgemm, const float* __restrict__ gamma,
          const float* __restrict__ beta) {
    extern __shared__ __align__(1024) char smem[];
    const uint32_t sb = smem_u32(smem);
    const int tid = threadIdx.x;
    const int wid = tid >> 5;
    const int lid = tid & 31;
    const int wm = wid >> 2;   // 0..1  (warp row block, 64 rows)
    const int wn = wid & 3;    // 0..3  (warp col block, 32 cols)

    const int n0 = blockIdx.x * BN;
    const int m0 = blockIdx.y * BM;

    float* sBg = reinterpret_cast<float*>(smem + SM_BG);
    float* sGa = reinterpret_cast<float*>(smem + SM_GA);
    float* sBe = reinterpret_cast<float*>(smem + SM_BE);
    if (tid < BN) {
        sBg[tid] = bgemm[n0 + tid];
        sGa[tid] = gamma[n0 + tid];
        sBe[tid] = beta[n0 + tid];
    }

    // ---- stage loader: 2048 x 16B chunks (A:1024, B:1024), one commit ----
    auto load_stage = [&](int s, int kk) {
        const uint32_t stage = sb + SM_STAGE + s * STAGE_BYTES;
#pragma unroll
        for (int c = tid; c < 2048; c += NTHREADS) {
            if (c < 1024) {
                int row = c >> 3, q = c & 7;  // 128 rows x 8 chunks
                const void* src = g_xh + (size_t)(m0 + row) * Kdim + kk + q * 8;
                uint32_t off = (uint32_t)(row * 128 + q * 16);
                cp_async16(stage + OFF_A + SWZ(off), src);
            } else {
                int t = c - 1024;
                int row = t >> 3, q = t & 7;  // 128 rows x 8 chunks
                const void* src = g_wh + (size_t)(n0 + row) * Kdim + kk + q * 8;
                uint32_t off = (uint32_t)(row * 128 + q * 16);
                cp_async16(stage + OFF_B + SWZ(off), src);
            }
        }
        cp_commit();
    };

    // Prologue: fill NSTAGE-1 stages
    load_stage(0, 0);
    load_stage(1, BK);

    float acc[4][4][4];
#pragma unroll
    for (int i = 0; i < 4; ++i)
#pragma unroll
        for (int j = 0; j < 4; ++j)
#pragma unroll
            for (int e = 0; e < 4; ++e) acc[i][j][e] = 0.f;

    // ldmatrix lane addressing (within 128B-row swizzled tiles)
    const int arow = (lid & 15);          // A: rows 0..15 of the m16 tile
    const int acolh = (lid >> 4) << 4;    // A: k-byte half (0 / 16)
    const int brow = ((lid >> 4) << 3) + (lid & 7);  // B: n row within n16 pair
    const int bcolh = ((lid >> 3) & 1) << 4;         // B: k-byte half

    // ---- mainloop: 32 K-slices, 3-stage cp.async pipeline, ONE sync/slice ----
    for (int it = 0; it < NSLICE; ++it) {
        const int s = it % NSTAGE;
        cp_wait<NSTAGE - 2>();
        __syncthreads();

        if (it + NSTAGE - 1 < NSLICE)
            load_stage((it + NSTAGE - 1) % NSTAGE, (it + NSTAGE - 1) * BK);
        else
            cp_commit();  // empty group: keep pending-group count consistent

        const uint32_t stage = sb + SM_STAGE + s * STAGE_BYTES;
        const uint32_t aBase = stage + OFF_A, bBase = stage + OFF_B;

#pragma unroll
        for (int ks = 0; ks < 4; ++ks) {
            const int kb = ks * 32;  // k-byte base within 128B row
            uint32_t af[4][4], bf[2][4];
#pragma unroll
            for (int i = 0; i < 4; ++i) {
                uint32_t off = (uint32_t)((wm * 64 + i * 16 + arow) * 128 + kb + acolh);
                ldsm_x4(af[i], aBase + SWZ(off));
            }
#pragma unroll
            for (int jj = 0; jj < 2; ++jj) {
                uint32_t off = (uint32_t)((wn * 32 + jj * 16 + brow) * 128 + kb + bcolh);
                ldsm_x4(bf[jj], bBase + SWZ(off));
            }
#pragma unroll
            for (int i = 0; i < 4; ++i)
#pragma unroll
                for (int j = 0; j < 4; ++j) {
                    const int jj = j >> 1, h = (j & 1) * 2;
                    mma_f16(acc[i][j], af[i], bf[jj][h], bf[jj][h + 1]);
                }
        }
    }

    // ---- epilogue: acc -> smem y[128][132] (+gemm bias), then GN + row-min ----
    cp_wait<0>();
    __syncthreads();  // all mma done; safe to overwrite stage smem
    float* ys = reinterpret_cast<float*>(smem + SM_STAGE);
    const int lg = lid >> 2;        // 0..7
    const int lc = (lid & 3) * 2;   // 0,2,4,6
#pragma unroll
    for (int i = 0; i < 4; ++i) {
        const int r0 = wm * 64 + i * 16 + lg;
#pragma unroll
        for (int j = 0; j < 4; ++j) {
            const int col = wn * 32 + j * 8 + lc;
            ys[r0 * YSTRIDE + col]           = acc[i][j][0] + sBg[col];
            ys[r0 * YSTRIDE + col + 1]       = acc[i][j][1] + sBg[col + 1];
            ys[(r0 + 8) * YSTRIDE + col]     = acc[i][j][2] + sBg[col];
            ys[(r0 + 8) * YSTRIDE + col + 1] = acc[i][j][3] + sBg[col + 1];
        }
    }
    __syncthreads();

    // one thread per row: 128 rows, BN=128 = exactly one GroupNorm group
    if (tid < BM) {
        const int base = tid * YSTRIDE;
        float s1 = 0.f, s2 = 0.f;
#pragma unroll 8
        for (int c = 0; c < 32; ++c) {
            float4 v = *reinterpret_cast<const float4*>(&ys[base + c * 4]);
            s1 += (v.x + v.y) + (v.z + v.w);
            s2 += v.x * v.x + v.y * v.y + v.z * v.z + v.w * v.w;
        }
        const float mean = s1 * (1.f / 128.f);
        const float var = fmaxf(s2 * (1.f / 128.f) - mean * mean, 0.f);
        const float rstd = rsqrtf(var + 1e-5f);

        float mn = 3.4e38f;
#pragma unroll 8
        for (int c = 0; c < 32; ++c) {
            float4 v = *reinterpret_cast<const float4*>(&ys[base + c * 4]);
            const int col = c * 4;
            float z0 = (v.x - mean) * rstd * sGa[col]     + sBe[col];
            float z1 = (v.y - mean) * rstd * sGa[col + 1] + sBe[col + 1];
            float z2 = (v.z - mean) * rstd * sGa[col + 2] + sBe[col + 2];
            float z3 = (v.w - mean) * rstd * sGa[col + 3] + sBe[col + 3];
            mn = fminf(mn, fminf(fminf(z0, z1), fminf(z2, z3)));
        }
        // order-preserving float->uint encoding, then atomicMin
        unsigned b = __float_as_uint(mn);
        unsigned u = (b & 0x80000000u) ? ~b : (b | 0x80000000u);
        atomicMin(&g_rowmin[m0 + tid], u);
    }
}

// ---------------------------------------------------------------------------
// Kernel 3: out[m, n] = decode(rowmin[m]) + bias[n]   (128 MB stream write)
// ---------------------------------------------------------------------------
__global__ void k_out(const float* __restrict__ bias, float* __restrict__ out) {
    int i = blockIdx.x * blockDim.x + threadIdx.x;  // float4 index
    constexpr int TOT4 = (Mdim * Ndim) / 4;
    if (i < TOT4) {
        const int m = i >> 10;
        const int n4 = i & 1023;
        unsigned u = g_rowmin[m];
        unsigned b = (u & 0x80000000u) ? (u & 0x7FFFFFFFu) : ~u;
        const float r = __uint_as_float(b);
        float4 bv = reinterpret_cast<const float4*>(bias)[n4];
        float4 o;
        o.x = r + bv.x; o.y = r + bv.y; o.z = r + bv.z; o.w = r + bv.w;
        reinterpret_cast<float4*>(out)[i] = o;
    }
}

// ---------------------------------------------------------------------------
extern "C" void kernel_launch(void* const* d_in, const int* in_sizes, int n_in,
                              void* d_out, int out_size) {
    const float* x     = (const float*)d_in[0];
    const float* W     = (const float*)d_in[1];
    const float* bgemm = (const float*)d_in[2];
    const float* gamma = (const float*)d_in[3];
    const float* beta  = (const float*)d_in[4];
    const float* bias  = (const float*)d_in[5];
    float* out = (float*)d_out;

    cudaFuncSetAttribute(k_gemm_gn, cudaFuncAttributeMaxDynamicSharedMemorySize,
                         SMEM_TOTAL);

    k_convert<<<(Mdim * Kdim / 4 + 255) / 256, 256>>>(x, W);
    dim3 grid(Ndim / BN, Mdim / BM);  // (32, 64) = 2048 CTAs, 2 per SM
    k_gemm_gn<<<grid, NTHREADS, SMEM_TOTAL>>>(bgemm, gamma, beta);
    k_out<<<(Mdim * Ndim / 4 + 255) / 256, 256>>>(bias, out);
}

// round 15
// speedup vs baseline: 1.1257x; 1.1257x over previous
#include <cuda_runtime.h>
#include <cuda_bf16.h>
#include <cuda_fp16.h>
#include <cstdint>

// ---------------------------------------------------------------------------
// Problem dims (fixed)
// ---------------------------------------------------------------------------
static constexpr int Mdim = 8192;
static constexpr int Kdim = 2048;
static constexpr int Ndim = 4096;

static constexpr int BM = 128;
static constexpr int BN = 128;            // exactly 1 GroupNorm group
static constexpr int BK = 64;             // fp16 -> 128B rows in smem (SW128)
static constexpr int NSLICE = Kdim / BK;  // 32
static constexpr int NSTAGE = 3;
static constexpr int NTHREADS = 256;      // 8 warps; 2 CTAs/SM -> 4 warps/SMSP

static constexpr int TILE_BYTES = 128 * 128;  // one 128-row x 64-col fp16 tile

// SW128 swizzle: XOR bits [6:4] with bits [9:7] (conflict-free on 128B rows
// for ldmatrix lane addresses). Applied at CONVERT time: scratch tensors are
// stored pre-swizzled in 16KB tiles so the GEMM can use linear bulk copies.
__host__ __device__ __forceinline__ uint32_t SWZ(uint32_t o) {
    return o ^ ((o >> 3) & 0x70u);
}

// ---------------------------------------------------------------------------
// Scratch (device globals — no runtime allocation allowed)
// g_xh: [Mdim/128][Kdim/64] tiles of 16KB (row*128 + kbyte, swizzled)
// g_wh: [Ndim/128][Kdim/64] tiles of 16KB
// ---------------------------------------------------------------------------
__device__ __align__(1024) __half g_xh[Mdim * Kdim];
__device__ __align__(1024) __half g_wh[Ndim * Kdim];
__device__ unsigned int g_rowmin[Mdim];  // order-preserving uint encoding

// ---------------------------------------------------------------------------
// PTX helpers (sm_90-compatible: cp.async.bulk, mbarrier, ldmatrix, mma.sync)
// ---------------------------------------------------------------------------
__device__ __forceinline__ uint32_t smem_u32(const void* p) {
    uint32_t a;
    asm("{ .reg .u64 t; cvta.to.shared.u64 t, %1; cvt.u32.u64 %0, t; }"
        : "=r"(a) : "l"(p));
    return a;
}
__device__ __forceinline__ void mbar_init(uint32_t a, uint32_t cnt) {
    asm volatile("mbarrier.init.shared.b64 [%0], %1;" :: "r"(a), "r"(cnt) : "memory");
}
__device__ __forceinline__ void mbar_expect_tx(uint32_t a, uint32_t bytes) {
    asm volatile("mbarrier.arrive.expect_tx.shared.b64 _, [%0], %1;"
                 :: "r"(a), "r"(bytes) : "memory");
}
__device__ __forceinline__ void mbar_wait(uint32_t a, uint32_t parity) {
    asm volatile(
        "{\n\t.reg .pred P;\n"
        "WL_%=:\n\t"
        "mbarrier.try_wait.parity.acquire.cta.shared::cta.b64 P, [%0], %1, 0x989680;\n\t"
        "@P bra WD_%=;\n\t"
        "bra WL_%=;\n"
        "WD_%=:\n\t}"
        :: "r"(a), "r"(parity) : "memory");
}
__device__ __forceinline__ void bulk_g2s(uint32_t sdst, const void* gsrc,
                                         uint32_t bytes, uint32_t mbar) {
    asm volatile(
        "cp.async.bulk.shared::cta.global.mbarrier::complete_tx::bytes "
        "[%0], [%1], %2, [%3];"
        :: "r"(sdst), "l"(gsrc), "r"(bytes), "r"(mbar) : "memory");
}
__device__ __forceinline__ void ldsm_x4(uint32_t (&r)[4], uint32_t addr) {
    asm volatile("ldmatrix.sync.aligned.m8n8.x4.shared.b16 {%0,%1,%2,%3}, [%4];"
                 : "=r"(r[0]), "=r"(r[1]), "=r"(r[2]), "=r"(r[3]) : "r"(addr));
}
__device__ __forceinline__ void mma_f16(float (&c)[4], const uint32_t (&a)[4],
                                        uint32_t b0, uint32_t b1) {
    asm volatile(
        "mma.sync.aligned.m16n8k16.row.col.f32.f16.f16.f32 "
        "{%0,%1,%2,%3}, {%4,%5,%6,%7}, {%8,%9}, {%0,%1,%2,%3};"
        : "+f"(c[0]), "+f"(c[1]), "+f"(c[2]), "+f"(c[3])
        : "r"(a[0]), "r"(a[1]), "r"(a[2]), "r"(a[3]), "r"(b0), "r"(b1));
}
__device__ __forceinline__ uint32_t h2u(__half2 h) {
    return *reinterpret_cast<uint32_t*>(&h);
}

// ---------------------------------------------------------------------------
// Kernel 1: fp32 -> fp16, written in pre-swizzled 16KB tile layout; init rowmin
// Each thread produces one 16B dst chunk (8 fp16) from 32B of fp32.
// ---------------------------------------------------------------------------
__global__ void k_convert(const float* __restrict__ x, const float* __restrict__ w) {
    const int i = blockIdx.x * blockDim.x + threadIdx.x;
    constexpr int XC = (Mdim * Kdim) / 8;  // 2,097,152 chunks
    constexpr int WC = (Ndim * Kdim) / 8;  // 1,048,576 chunks
    constexpr int KSL = Kdim / BK;         // 32

    if (i < XC) {
        const int q = i & 7, row = (i >> 3) & 127, blk = i >> 10;  // blk=[mblk*32+ks]
        const int rg = (blk >> 5) * 128 + row;
        const int k0 = (blk & 31) * BK + q * 8;
        const float4* s = reinterpret_cast<const float4*>(x + (size_t)rg * Kdim + k0);
        float4 v0 = s[0], v1 = s[1];
        uint4 o;
        o.x = h2u(__floats2half2_rn(v0.x, v0.y));
        o.y = h2u(__floats2half2_rn(v0.z, v0.w));
        o.z = h2u(__floats2half2_rn(v1.x, v1.y));
        o.w = h2u(__floats2half2_rn(v1.z, v1.w));
        char* dst = reinterpret_cast<char*>(g_xh) + (size_t)blk * TILE_BYTES +
                    SWZ((uint32_t)(row * 128 + q * 16));
        *reinterpret_cast<uint4*>(dst) = o;
    }
    if (i < WC) {
        const int q = i & 7, row = (i >> 3) & 127, blk = i >> 10;  // blk=[nblk*32+ks]
        const int rg = (blk >> 5) * 128 + row;
        const int k0 = (blk & 31) * BK + q * 8;
        const float4* s = reinterpret_cast<const float4*>(w + (size_t)rg * Kdim + k0);
        float4 v0 = s[0], v1 = s[1];
        uint4 o;
        o.x = h2u(__floats2half2_rn(v0.x, v0.y));
        o.y = h2u(__floats2half2_rn(v0.z, v0.w));
        o.z = h2u(__floats2half2_rn(v1.x, v1.y));
        o.w = h2u(__floats2half2_rn(v1.z, v1.w));
        char* dst = reinterpret_cast<char*>(g_wh) + (size_t)blk * TILE_BYTES +
                    SWZ((uint32_t)(row * 128 + q * 16));
        *reinterpret_cast<uint4*>(dst) = o;
    }
    if (i < Mdim) g_rowmin[i] = 0xFFFFFFFFu;
    (void)KSL;
}

// ---------------------------------------------------------------------------
// Kernel 2: fp16 mma.sync GEMM (bulk-copy pipeline) + fused GN/row-min epilogue
// ---------------------------------------------------------------------------
// smem layout (dynamic, 1024-aligned), 100 KB total -> 2 CTAs/SM:
//   [0..]       bgemm[128], gamma[128], beta[128] f32
//   [3072..]    mbar[3] (8B each)
//   [4096..]    3 stages x 32KB:  A 16K | B 16K
//   epilogue reuses [4096..] as y[128][132] f32 (67,584 B)
static constexpr int SM_BG    = 0;
static constexpr int SM_GA    = 1024;
static constexpr int SM_BE    = 2048;
static constexpr int SM_MBAR  = 3072;
static constexpr int SM_STAGE = 4096;
static constexpr int STAGE_BYTES = 32 * 1024;
static constexpr int OFF_A = 0;
static constexpr int OFF_B = 16384;
static constexpr int SMEM_TOTAL = SM_STAGE + NSTAGE * STAGE_BYTES;  // 102400
static constexpr int YSTRIDE = 132;

__global__ void __launch_bounds__(NTHREADS, 2)
k_gemm_gn(const float* __restrict__ bgemm, const float* __restrict__ gamma,
          const float* __restrict__ beta) {
    extern __shared__ __align__(1024) char smem[];
    const uint32_t sb = smem_u32(smem);
    const int tid = threadIdx.x;
    const int wid = tid >> 5;
    const int lid = tid & 31;
    const int wm = wid >> 2;   // 0..1  (warp row block, 64 rows)
    const int wn = wid & 3;    // 0..3  (warp col block, 32 cols)

    const int n0 = blockIdx.x * BN;
    const int m0 = blockIdx.y * BM;

    float* sBg = reinterpret_cast<float*>(smem + SM_BG);
    float* sGa = reinterpret_cast<float*>(smem + SM_GA);
    float* sBe = reinterpret_cast<float*>(smem + SM_BE);
    if (tid < BN) {
        sBg[tid] = bgemm[n0 + tid];
        sGa[tid] = gamma[n0 + tid];
        sBe[tid] = beta[n0 + tid];
    }

    // ---- bulk-copy slice issue: 2 ops, thread 0 only ----
    auto issue_slice = [&](int slice) {
        const int s = slice % NSTAGE;
        const uint32_t stage = sb + SM_STAGE + s * STAGE_BYTES;
        const uint32_t mb = sb + SM_MBAR + s * 8;
        mbar_expect_tx(mb, 2 * TILE_BYTES);
        const char* gA = reinterpret_cast<const char*>(g_xh) +
                         (size_t)(blockIdx.y * NSLICE + slice) * TILE_BYTES;
        const char* gB = reinterpret_cast<const char*>(g_wh) +
                         (size_t)(blockIdx.x * NSLICE + slice) * TILE_BYTES;
        bulk_g2s(stage + OFF_A, gA, TILE_BYTES, mb);
        bulk_g2s(stage + OFF_B, gB, TILE_BYTES, mb);
    };

    if (tid == 0) {
        mbar_init(sb + SM_MBAR + 0, 1);
        mbar_init(sb + SM_MBAR + 8, 1);
        mbar_init(sb + SM_MBAR + 16, 1);
    }
    __syncthreads();
    if (tid == 0) {
        issue_slice(0);
        issue_slice(1);
    }

    float acc[4][4][4];
#pragma unroll
    for (int i = 0; i < 4; ++i)
#pragma unroll
        for (int j = 0; j < 4; ++j)
#pragma unroll
            for (int e = 0; e < 4; ++e) acc[i][j][e] = 0.f;

    // ldmatrix lane addressing (within 128B-row swizzled tiles)
    const int arow = (lid & 15);          // A: rows 0..15 of the m16 tile
    const int acolh = (lid >> 4) << 4;    // A: k-byte half (0 / 16)
    const int brow = ((lid >> 4) << 3) + (lid & 7);  // B: n row within n16 pair
    const int bcolh = ((lid >> 3) & 1) << 4;         // B: k-byte half

    // ---- mainloop: 32 K-slices, 3-stage bulk pipeline, ONE sync/slice ----
    for (int it = 0; it < NSLICE; ++it) {
        const int s = it % NSTAGE;
        mbar_wait(sb + SM_MBAR + s * 8, (uint32_t)((it / NSTAGE) & 1));
        __syncthreads();  // all threads done reading stage (it+2)%3 (slice it-1)

        if (tid == 0 && it + 2 < NSLICE) issue_slice(it + 2);

        const uint32_t stage = sb + SM_STAGE + s * STAGE_BYTES;
        const uint32_t aBase = stage + OFF_A, bBase = stage + OFF_B;

#pragma unroll
        for (int ks = 0; ks < 4; ++ks) {
            const int kb = ks * 32;  // k-byte base within 128B row
            uint32_t af[4][4], bf[2][4];
#pragma unroll
            for (int i = 0; i < 4; ++i) {
                uint32_t off = (uint32_t)((wm * 64 + i * 16 + arow) * 128 + kb + acolh);
                ldsm_x4(af[i], aBase + SWZ(off));
            }
#pragma unroll
            for (int jj = 0; jj < 2; ++jj) {
                uint32_t off = (uint32_t)((wn * 32 + jj * 16 + brow) * 128 + kb + bcolh);
                ldsm_x4(bf[jj], bBase + SWZ(off));
            }
#pragma unroll
            for (int i = 0; i < 4; ++i)
#pragma unroll
                for (int j = 0; j < 4; ++j) {
                    const int jj = j >> 1, h = (j & 1) * 2;
                    mma_f16(acc[i][j], af[i], bf[jj][h], bf[jj][h + 1]);
                }
        }
    }

    // ---- epilogue: acc -> smem y[128][132] (+gemm bias), then GN + row-min ----
    __syncthreads();  // all mma done; safe to overwrite stage smem
    float* ys = reinterpret_cast<float*>(smem + SM_STAGE);
    const int lg = lid >> 2;        // 0..7
    const int lc = (lid & 3) * 2;   // 0,2,4,6
#pragma unroll
    for (int i = 0; i < 4; ++i) {
        const int r0 = wm * 64 + i * 16 + lg;
#pragma unroll
        for (int j = 0; j < 4; ++j) {
            const int col = wn * 32 + j * 8 + lc;
            ys[r0 * YSTRIDE + col]           = acc[i][j][0] + sBg[col];
            ys[r0 * YSTRIDE + col + 1]       = acc[i][j][1] + sBg[col + 1];
            ys[(r0 + 8) * YSTRIDE + col]     = acc[i][j][2] + sBg[col];
            ys[(r0 + 8) * YSTRIDE + col + 1] = acc[i][j][3] + sBg[col + 1];
        }
    }
    __syncthreads();

    // one thread per row: 128 rows, BN=128 = exactly one GroupNorm group
    if (tid < BM) {
        const int base = tid * YSTRIDE;
        float s1 = 0.f, s2 = 0.f;
#pragma unroll 8
        for (int c = 0; c < 32; ++c) {
            float4 v = *reinterpret_cast<const float4*>(&ys[base + c * 4]);
            s1 += (v.x + v.y) + (v.z + v.w);
            s2 += v.x * v.x + v.y * v.y + v.z * v.z + v.w * v.w;
        }
        const float mean = s1 * (1.f / 128.f);
        const float var = fmaxf(s2 * (1.f / 128.f) - mean * mean, 0.f);
        const float rstd = rsqrtf(var + 1e-5f);

        float mn = 3.4e38f;
#pragma unroll 8
        for (int c = 0; c < 32; ++c) {
            float4 v = *reinterpret_cast<const float4*>(&ys[base + c * 4]);
            const int col = c * 4;
            float z0 = (v.x - mean) * rstd * sGa[col]     + sBe[col];
            float z1 = (v.y - mean) * rstd * sGa[col + 1] + sBe[col + 1];
            float z2 = (v.z - mean) * rstd * sGa[col + 2] + sBe[col + 2];
            float z3 = (v.w - mean) * rstd * sGa[col + 3] + sBe[col + 3];
            mn = fminf(mn, fminf(fminf(z0, z1), fminf(z2, z3)));
        }
        // order-preserving float->uint encoding, then atomicMin
        unsigned b = __float_as_uint(mn);
        unsigned u = (b & 0x80000000u) ? ~b : (b | 0x80000000u);
        atomicMin(&g_rowmin[m0 + tid], u);
    }
}

// ---------------------------------------------------------------------------
// Kernel 3: out[m, n] = decode(rowmin[m]) + bias[n]   (128 MB stream write)
// ---------------------------------------------------------------------------
__global__ void k_out(const float* __restrict__ bias, float* __restrict__ out) {
    int i = blockIdx.x * blockDim.x + threadIdx.x;  // float4 index
    constexpr int TOT4 = (Mdim * Ndim) / 4;
    if (i < TOT4) {
        const int m = i >> 10;
        const int n4 = i & 1023;
        unsigned u = g_rowmin[m];
        unsigned b = (u & 0x80000000u) ? (u & 0x7FFFFFFFu) : ~u;
        const float r = __uint_as_float(b);
        float4 bv = reinterpret_cast<const float4*>(bias)[n4];
        float4 o;
        o.x = r + bv.x; o.y = r + bv.y; o.z = r + bv.z; o.w = r + bv.w;
        reinterpret_cast<float4*>(out)[i] = o;
    }
}

// ---------------------------------------------------------------------------
extern "C" void kernel_launch(void* const* d_in, const int* in_sizes, int n_in,
                              void* d_out, int out_size) {
    const float* x     = (const float*)d_in[0];
    const float* W     = (const float*)d_in[1];
    const float* bgemm = (const float*)d_in[2];
    const float* gamma = (const float*)d_in[3];
    const float* beta  = (const float*)d_in[4];
    const float* bias  = (const float*)d_in[5];
    float* out = (float*)d_out;

    cudaFuncSetAttribute(k_gemm_gn, cudaFuncAttributeMaxDynamicSharedMemorySize,
                         SMEM_TOTAL);

    k_convert<<<(Mdim * Kdim / 8 + 255) / 256, 256>>>(x, W);
    dim3 grid(Ndim / BN, Mdim / BM);  // (32, 64) = 2048 CTAs, 2 per SM
    k_gemm_gn<<<grid, NTHREADS, SMEM_TOTAL>>>(bgemm, gamma, beta);
    k_out<<<(Mdim * Ndim / 4 + 255) / 256, 256>>>(bias, out);
}